// round 9
// baseline (speedup 1.0000x reference)
#include <cuda_runtime.h>
#include <cstdint>

// GaussianTrans via mma.sync tf32 (arch-agnostic PTX; tcgen05 is 'a'-gated).
//   outX[b,r,c,d] = sum_h sig(disX+attX) * V[b,r,h,d]   (pass X: write)
//   outY[b,r,c,d] = sum_w sig(disY+attY) * V[b,w,c,d]   (pass Y: accumulate)
// B=16, H=W=64, D=512.
// CTA = (outer, b): full 64m x 512n x 64k. A tile built once; V streamed in
// 4 chunks of 128-d via 2-deep cp.async double buffer; per-chunk epilogue
// overlaps the next chunk's loads. 256 threads = 8 warps, each 64m x 16n.
// X/Y launches interleaved per 4 batches so pass Y's V + outX RMW hit L2.

#define SK 68    // As row stride (pad 4)
#define SN 136   // V chunk row stride (pad 8)

static constexpr uint32_t SMEM_BYTES = (64 * SK + 2 * 64 * SN) * 4;  // 87040

static __device__ __forceinline__ uint32_t tf32rn(float f) {
    uint32_t r;
    asm("cvt.rn.tf32.f32 %0, %1;" : "=r"(r) : "f"(f));
    return r;
}
static __device__ __forceinline__ float fast_sigmoid(float t) {
    return __fdividef(1.0f, 1.0f + __expf(-t));
}
static __device__ __forceinline__ uint32_t smem_u32(const void* p) {
    uint32_t a;
    asm("{ .reg .u64 t; cvta.to.shared.u64 t, %1; cvt.u32.u64 %0, t; }"
        : "=r"(a) : "l"(p));
    return a;
}
static __device__ __forceinline__ void mma_tf32(float& c0, float& c1, float& c2,
                                                float& c3, uint32_t a0, uint32_t a1,
                                                uint32_t a2, uint32_t a3,
                                                uint32_t b0, uint32_t b1) {
    asm volatile(
        "mma.sync.aligned.m16n8k8.row.col.f32.tf32.tf32.f32 "
        "{%0,%1,%2,%3}, {%4,%5,%6,%7}, {%8,%9}, {%0,%1,%2,%3};"
        : "+f"(c0), "+f"(c1), "+f"(c2), "+f"(c3)
        : "r"(a0), "r"(a1), "r"(a2), "r"(a3), "r"(b0), "r"(b1));
}

template<bool PASSY>
__global__ __launch_bounds__(256, 2)
void gt_mma(const float* __restrict__ att, const float* __restrict__ V,
            float* __restrict__ out, const float* __restrict__ shift,
            const float* __restrict__ bias, int b0)
{
    extern __shared__ float smem[];
    float* As = smem;                       // [64][SK], tf32-RN
    float* Vb[2] = { smem + 64 * SK,        // [64][SN] raw fp32 chunk buffers
                     smem + 64 * SK + 64 * SN };

    const int tid = threadIdx.x;
    const int outer = blockIdx.x;           // r (pass X) or c (pass Y)
    const int b     = b0 + blockIdx.y;      // 4 batches per launch

    const float sh = shift[0], bi = bias[0];
    const int attBase = (b * 64 + outer) * 4096;
    const int off     = PASSY ? (b * 2097152 + outer * 512)
                              : ((b * 64 + outer) * 32768);
    const int vstride = PASSY ? 32768 : 512;

    const uint32_t vsb0 = smem_u32(Vb[0]);
    const uint32_t vsb1 = smem_u32(Vb[1]);

    // 512 float4 per chunk / 256 threads = 2 per thread
    const int vrow  = tid >> 3;                  // 0..31 -> rows tid>>3, +32
    const int vcol  = (tid & 7) << 2;            // 0,4,...,28 -> +0 / +16 words... 
    // (each thread: rows vrow and vrow+32, cols vcol*? ) use flat mapping below.

    auto issueChunk = [&](int ch, uint32_t vsb) {
        const float* srcBase = V + off + ch * 128;
        #pragma unroll
        for (int j = 0; j < 8; ++j) {
            const int idx4 = tid + j * 256;      // 2048 float4 per chunk
            const int row  = idx4 >> 5;
            const int col  = (idx4 & 31) << 2;
            const float* src = srcBase + row * vstride + col;
            const uint32_t dst = vsb + (uint32_t)(row * SN + col) * 4u;
            asm volatile("cp.async.cg.shared.global [%0], [%1], 16;"
                         :: "r"(dst), "l"(src) : "memory");
        }
        asm volatile("cp.async.commit_group;" ::: "memory");
    };

    // ---- prime: chunk 0 in flight, then build A (overlaps) ----
    issueChunk(0, vsb0);

    #pragma unroll
    for (int j = 0; j < 4; ++j) {
        const int idx4 = tid + j * 256;          // 1024 float4 = 4096 elems
        const int m  = idx4 >> 4;
        const int k4 = (idx4 & 15) << 2;
        const float4 av = *reinterpret_cast<const float4*>(att + attBase + idx4 * 4);
        float d0 = (float)(k4 + 0 - m);
        float d1 = (float)(k4 + 1 - m);
        float d2 = (float)(k4 + 2 - m);
        float d3 = (float)(k4 + 3 - m);
        uint4 sv;
        sv.x = tf32rn(fast_sigmoid(fmaf(-sh * d0, d0, av.x - bi)));
        sv.y = tf32rn(fast_sigmoid(fmaf(-sh * d1, d1, av.y - bi)));
        sv.z = tf32rn(fast_sigmoid(fmaf(-sh * d2, d2, av.z - bi)));
        sv.w = tf32rn(fast_sigmoid(fmaf(-sh * d3, d3, av.w - bi)));
        *reinterpret_cast<uint4*>(&As[m * SK + k4]) = sv;
    }

    const int wid  = tid >> 5;
    const int lane = tid & 31;
    const int grp  = lane >> 2;     // 0..7
    const int tig  = lane & 3;      // 0..3
    const int n0   = wid * 16;      // 8 warps x 16n = 128

    const uint32_t* Au = reinterpret_cast<const uint32_t*>(As);

    // ---- 4 chunks, double-buffered ----
    #pragma unroll
    for (int ch = 0; ch < 4; ++ch) {
        if (ch < 3) issueChunk(ch + 1, (ch & 1) ? vsb0 : vsb1);
        if (ch < 3) asm volatile("cp.async.wait_group 1;" ::: "memory");
        else        asm volatile("cp.async.wait_group 0;" ::: "memory");
        __syncthreads();

        const uint32_t* Vu = reinterpret_cast<const uint32_t*>(Vb[ch & 1]);

        float acc[4][2][4];
        #pragma unroll
        for (int mt = 0; mt < 4; ++mt)
            #pragma unroll
            for (int nt = 0; nt < 2; ++nt)
                #pragma unroll
                for (int q = 0; q < 4; ++q) acc[mt][nt][q] = 0.0f;

        #pragma unroll
        for (int k8 = 0; k8 < 8; ++k8) {
            const int kb = k8 * 8;
            uint32_t a[4][4];
            #pragma unroll
            for (int mt = 0; mt < 4; ++mt) {
                const int base = (mt * 16 + grp) * SK + kb + tig;
                a[mt][0] = Au[base];
                a[mt][1] = Au[base + 8 * SK];
                a[mt][2] = Au[base + 4];
                a[mt][3] = Au[base + 8 * SK + 4];
            }
            #pragma unroll
            for (int nt = 0; nt < 2; ++nt) {
                const int nc = n0 + nt * 8 + grp;
                const uint32_t bq0 = Vu[(kb + tig) * SN + nc];
                const uint32_t bq1 = Vu[(kb + tig + 4) * SN + nc];
                #pragma unroll
                for (int mt = 0; mt < 4; ++mt)
                    mma_tf32(acc[mt][nt][0], acc[mt][nt][1],
                             acc[mt][nt][2], acc[mt][nt][3],
                             a[mt][0], a[mt][1], a[mt][2], a[mt][3], bq0, bq1);
            }
        }

        // per-chunk epilogue (overlaps next chunk's cp.async)
        #pragma unroll
        for (int mt = 0; mt < 4; ++mt) {
            #pragma unroll
            for (int nt = 0; nt < 2; ++nt) {
                const int col  = ch * 128 + n0 + nt * 8 + tig * 2;
                const int row0 = mt * 16 + grp;
                float* p0 = out + off + row0 * vstride + col;
                float* p1 = p0 + 8 * vstride;
                float2 w0 = make_float2(acc[mt][nt][0], acc[mt][nt][1]);
                float2 w1 = make_float2(acc[mt][nt][2], acc[mt][nt][3]);
                if (PASSY) {
                    const float2 o0 = *reinterpret_cast<const float2*>(p0);
                    const float2 o1 = *reinterpret_cast<const float2*>(p1);
                    w0.x += o0.x; w0.y += o0.y;
                    w1.x += o1.x; w1.y += o1.y;
                }
                *reinterpret_cast<float2*>(p0) = w0;
                *reinterpret_cast<float2*>(p1) = w1;
            }
        }
        __syncthreads();   // buffer (ch&1) safe to overwrite next iteration
    }
}

extern "C" void kernel_launch(void* const* d_in, const int* in_sizes, int n_in,
                              void* d_out, int out_size) {
    (void)in_sizes; (void)n_in; (void)out_size;
    // metadata order: x(unused), attentionXFull, attentionYFull, valueFull, shift, bias
    const float* attX  = (const float*)d_in[1];
    const float* attY  = (const float*)d_in[2];
    const float* V     = (const float*)d_in[3];
    const float* shift = (const float*)d_in[4];
    const float* bias  = (const float*)d_in[5];
    float* out = (float*)d_out;

    cudaFuncSetAttribute(gt_mma<false>,
                         cudaFuncAttributeMaxDynamicSharedMemorySize, SMEM_BYTES);
    cudaFuncSetAttribute(gt_mma<true>,
                         cudaFuncAttributeMaxDynamicSharedMemorySize, SMEM_BYTES);

    dim3 grid(64, 4);   // (outer, 4 batches)
    dim3 block(256);
    for (int b0 = 0; b0 < 16; b0 += 4) {
        gt_mma<false><<<grid, block, SMEM_BYTES>>>(attX, V, out, shift, bias, b0);
        gt_mma<true ><<<grid, block, SMEM_BYTES>>>(attY, V, out, shift, bias, b0);
    }
}

// round 10
// speedup vs baseline: 1.2961x; 1.2961x over previous
#include <cuda_runtime.h>
#include <cstdint>

// GaussianTrans via mma.sync tf32 (arch-agnostic PTX; tcgen05 is 'a'-gated).
//   outX[b,r,c,d] = sum_h sig(disX+attX) * V[b,r,h,d]   (pass X: write)
//   outY[b,r,c,d] = sum_w sig(disY+attY) * V[b,w,c,d]   (pass Y: accumulate)
// B=16, H=W=64, D=512.
// R5 structure, occupancy-tuned: CTA = 64m x 64n x 64k (d-tile 64), grid 2048
// per launch, 4 warps each 32m x 32n -> 32 accs, ~5 CTAs/SM (20 warps/SM).
// X/Y launches interleaved per 4 batches so pass Y's V + outX RMW hit L2.

#define SK 68    // As row stride (pad 4): lane bank = grp*4+tig, conflict-free
#define SN 72    // Vs row stride (pad 8): lane bank = tig*8+grp, conflict-free

static constexpr uint32_t SMEM_BYTES = (64 * SK + 64 * SN) * 4;  // 35840

static __device__ __forceinline__ uint32_t tf32rn(float f) {
    uint32_t r;
    asm("cvt.rn.tf32.f32 %0, %1;" : "=r"(r) : "f"(f));
    return r;
}
static __device__ __forceinline__ float fast_sigmoid(float t) {
    return __fdividef(1.0f, 1.0f + __expf(-t));
}
static __device__ __forceinline__ void mma_tf32(float& c0, float& c1, float& c2,
                                                float& c3, uint32_t a0, uint32_t a1,
                                                uint32_t a2, uint32_t a3,
                                                uint32_t b0, uint32_t b1) {
    asm volatile(
        "mma.sync.aligned.m16n8k8.row.col.f32.tf32.tf32.f32 "
        "{%0,%1,%2,%3}, {%4,%5,%6,%7}, {%8,%9}, {%0,%1,%2,%3};"
        : "+f"(c0), "+f"(c1), "+f"(c2), "+f"(c3)
        : "r"(a0), "r"(a1), "r"(a2), "r"(a3), "r"(b0), "r"(b1));
}

template<bool PASSY>
__global__ __launch_bounds__(128, 5)
void gt_mma(const float* __restrict__ att, const float* __restrict__ V,
            float* __restrict__ out, const float* __restrict__ shift,
            const float* __restrict__ bias, int b0)
{
    extern __shared__ float smem[];
    float* As = smem;             // [64][SK], tf32-RN bit patterns
    float* Vs = smem + 64 * SK;   // [64][SN], raw fp32 (HW truncates to tf32)

    const int tid = threadIdx.x;
    const int dt    = blockIdx.x;          // 0..7 (d tile of 64)
    const int outer = blockIdx.y;          // r (pass X) or c (pass Y)
    const int b     = b0 + blockIdx.z;     // 4 batches per launch

    const float sh = shift[0], bi = bias[0];
    const int attBase = (b * 64 + outer) * 4096;
    const int off     = PASSY ? (b * 2097152 + outer * 512)
                              : ((b * 64 + outer) * 32768);
    const int vstride = PASSY ? 32768 : 512;
    const int dbase   = dt * 64;

    // --- A tile: sigmoid(dis + att) -> tf32-RN; coalesced float4 in ---
    #pragma unroll
    for (int j = 0; j < 8; ++j) {
        const int idx4 = tid + j * 128;          // 1024 float4 = 4096 elems
        const int m  = idx4 >> 4;
        const int k4 = (idx4 & 15) << 2;
        const float4 av = *reinterpret_cast<const float4*>(att + attBase + idx4 * 4);
        float d0 = (float)(k4 + 0 - m);
        float d1 = (float)(k4 + 1 - m);
        float d2 = (float)(k4 + 2 - m);
        float d3 = (float)(k4 + 3 - m);
        uint4 sv;
        sv.x = tf32rn(fast_sigmoid(fmaf(-sh * d0, d0, av.x - bi)));
        sv.y = tf32rn(fast_sigmoid(fmaf(-sh * d1, d1, av.y - bi)));
        sv.z = tf32rn(fast_sigmoid(fmaf(-sh * d2, d2, av.z - bi)));
        sv.w = tf32rn(fast_sigmoid(fmaf(-sh * d3, d3, av.w - bi)));
        *reinterpret_cast<uint4*>(&As[m * SK + k4]) = sv;
    }

    // --- V tile: 64 k-rows x 64 d, raw fp32 bits ---
    #pragma unroll
    for (int j = 0; j < 8; ++j) {
        const int idx4 = tid + j * 128;          // 1024 float4
        const int row  = idx4 >> 4;
        const int col  = (idx4 & 15) << 2;
        const float4 vv = *reinterpret_cast<const float4*>(
            V + off + row * vstride + dbase + col);
        *reinterpret_cast<float4*>(&Vs[row * SN + col]) = vv;
    }
    __syncthreads();

    // --- mma.sync m16n8k8 tf32: warp = 32m x 32n (2 m-tiles x 4 n-tiles) ---
    const int wid  = tid >> 5;
    const int lane = tid & 31;
    const int grp  = lane >> 2;     // 0..7
    const int tig  = lane & 3;      // 0..3
    const int mrow = (wid & 1) * 32;
    const int n0   = (wid >> 1) * 32;

    float acc[2][4][4];
    #pragma unroll
    for (int mt = 0; mt < 2; ++mt)
        #pragma unroll
        for (int nt = 0; nt < 4; ++nt)
            #pragma unroll
            for (int q = 0; q < 4; ++q) acc[mt][nt][q] = 0.0f;

    const uint32_t* Au = reinterpret_cast<const uint32_t*>(As);
    const uint32_t* Vu = reinterpret_cast<const uint32_t*>(Vs);

    #pragma unroll
    for (int k8 = 0; k8 < 8; ++k8) {
        const int kb = k8 * 8;
        uint32_t a[2][4];
        #pragma unroll
        for (int mt = 0; mt < 2; ++mt) {
            const int base = (mrow + mt * 16 + grp) * SK + kb + tig;
            a[mt][0] = Au[base];                 // (row,   col)
            a[mt][1] = Au[base + 8 * SK];        // (row+8, col)
            a[mt][2] = Au[base + 4];             // (row,   col+4)
            a[mt][3] = Au[base + 8 * SK + 4];    // (row+8, col+4)
        }
        #pragma unroll
        for (int nt = 0; nt < 4; ++nt) {
            const int nc = n0 + nt * 8 + grp;
            const uint32_t bq0 = Vu[(kb + tig) * SN + nc];
            const uint32_t bq1 = Vu[(kb + tig + 4) * SN + nc];
            #pragma unroll
            for (int mt = 0; mt < 2; ++mt)
                mma_tf32(acc[mt][nt][0], acc[mt][nt][1],
                         acc[mt][nt][2], acc[mt][nt][3],
                         a[mt][0], a[mt][1], a[mt][2], a[mt][3], bq0, bq1);
        }
    }

    // --- epilogue: c0,c1 -> (row, 2 cols); c2,c3 -> (row+8, 2 cols) ---
    #pragma unroll
    for (int mt = 0; mt < 2; ++mt) {
        #pragma unroll
        for (int nt = 0; nt < 4; ++nt) {
            const int col  = dbase + n0 + nt * 8 + tig * 2;
            const int row0 = mrow + mt * 16 + grp;
            float* p0 = out + off + row0 * vstride + col;
            float* p1 = p0 + 8 * vstride;
            float2 w0 = make_float2(acc[mt][nt][0], acc[mt][nt][1]);
            float2 w1 = make_float2(acc[mt][nt][2], acc[mt][nt][3]);
            if (PASSY) {
                const float2 o0 = *reinterpret_cast<const float2*>(p0);
                const float2 o1 = *reinterpret_cast<const float2*>(p1);
                w0.x += o0.x; w0.y += o0.y;
                w1.x += o1.x; w1.y += o1.y;
            }
            *reinterpret_cast<float2*>(p0) = w0;
            *reinterpret_cast<float2*>(p1) = w1;
        }
    }
}

extern "C" void kernel_launch(void* const* d_in, const int* in_sizes, int n_in,
                              void* d_out, int out_size) {
    (void)in_sizes; (void)n_in; (void)out_size;
    // metadata order: x(unused), attentionXFull, attentionYFull, valueFull, shift, bias
    const float* attX  = (const float*)d_in[1];
    const float* attY  = (const float*)d_in[2];
    const float* V     = (const float*)d_in[3];
    const float* shift = (const float*)d_in[4];
    const float* bias  = (const float*)d_in[5];
    float* out = (float*)d_out;

    cudaFuncSetAttribute(gt_mma<false>,
                         cudaFuncAttributeMaxDynamicSharedMemorySize, SMEM_BYTES);
    cudaFuncSetAttribute(gt_mma<true>,
                         cudaFuncAttributeMaxDynamicSharedMemorySize, SMEM_BYTES);

    dim3 grid(8, 64, 4);   // (d-tile of 64, outer, 4 batches) = 2048 CTAs
    dim3 block(128);
    // Interleave per 4 batches: pass Y hits V[b] and outX[b] in L2.
    for (int b0 = 0; b0 < 16; b0 += 4) {
        gt_mma<false><<<grid, block, SMEM_BYTES>>>(attX, V, out, shift, bias, b0);
        gt_mma<true ><<<grid, block, SMEM_BYTES>>>(attY, V, out, shift, bias, b0);
    }
}